// round 11
// baseline (speedup 1.0000x reference)
#include <cuda_runtime.h>
#include <cuda_bf16.h>
#include <cuda_fp16.h>
#include <cstdint>

constexpr int kN = 100000;
constexpr int kE = 1600000;
constexpr int kG = 2048;
constexpr int kD = 128;
constexpr int kScanBlocks = (kN + 1023) / 1024; // 98

// ---------------- scratch (no allocations allowed) ----------------
__device__ __half g_h16a[kN * kD];           // h ping buffer, fp16 (pre-scaled)
__device__ __half g_h16b[kN * kD];           // h pong buffer, fp16 (pre-scaled)
__device__ __half g_whi[3 * kD * kD];        // W fp16 hi, [K][N]
__device__ __half g_wlo[3 * kD * kD];        // W fp16 lo, [K][N]
__device__ float g_inv_src[kN];
__device__ float g_inv_dst[kN];
__device__ int   g_deg_out[kN];
__device__ int   g_deg_in[kN];
__device__ int   g_row_ptr[kN + 1];
__device__ int   g_cursor[kN];
__device__ int   g_edge_src[kE];
__device__ int   g_blk[kScanBlocks];
__device__ float g_emb[kG * kD];
__device__ int   g_gcnt[kG];
__device__ float g_x1[kG * 512];
__device__ float g_x2[kG * 256];

// ---------------- mma / ldmatrix helpers (base ISA, sm_80+) ----------------
__device__ __forceinline__ uint32_t smem_u32(const void* p) {
    uint32_t a;
    asm("{ .reg .u64 t; cvta.to.shared.u64 t, %1; cvt.u32.u64 %0, t; }" : "=r"(a) : "l"(p));
    return a;
}
__device__ __forceinline__ void ldsm_x4(uint32_t* r, uint32_t addr) {
    asm volatile("ldmatrix.sync.aligned.m8n8.x4.shared.b16 {%0,%1,%2,%3}, [%4];"
                 : "=r"(r[0]), "=r"(r[1]), "=r"(r[2]), "=r"(r[3]) : "r"(addr));
}
__device__ __forceinline__ void ldsm_x4_t(uint32_t* r, uint32_t addr) {
    asm volatile("ldmatrix.sync.aligned.m8n8.x4.trans.shared.b16 {%0,%1,%2,%3}, [%4];"
                 : "=r"(r[0]), "=r"(r[1]), "=r"(r[2]), "=r"(r[3]) : "r"(addr));
}
__device__ __forceinline__ void mma16816h(float* d, const uint32_t* a, const uint32_t* b) {
    asm volatile(
        "mma.sync.aligned.m16n8k16.row.col.f32.f16.f16.f32 "
        "{%0,%1,%2,%3}, {%4,%5,%6,%7}, {%8,%9}, {%0,%1,%2,%3};"
        : "+f"(d[0]), "+f"(d[1]), "+f"(d[2]), "+f"(d[3])
        : "r"(a[0]), "r"(a[1]), "r"(a[2]), "r"(a[3]), "r"(b[0]), "r"(b[1]));
}

// ---------------- setup kernels ----------------
__global__ void k_zero() {
    int i = blockIdx.x * blockDim.x + threadIdx.x;
    if (i < kN) { g_deg_out[i] = 0; g_deg_in[i] = 0; }
    if (i < kG * kD) g_emb[i] = 0.f;
    if (i < kG) g_gcnt[i] = 0;
}

__global__ void k_degrees(const int* __restrict__ src, const int* __restrict__ dst) {
    int e = blockIdx.x * blockDim.x + threadIdx.x;
    if (e >= kE) return;
    atomicAdd(&g_deg_out[src[e]], 1);
    atomicAdd(&g_deg_in[dst[e]], 1);
}

__global__ void k_scan1() {
    __shared__ int sm[1024];
    int tid = threadIdx.x;
    int i = blockIdx.x * 1024 + tid;
    int v = (i < kN) ? g_deg_in[i] : 0;
    int x = v;
    sm[tid] = x;
    __syncthreads();
    for (int off = 1; off < 1024; off <<= 1) {
        int y = (tid >= off) ? sm[tid - off] : 0;
        __syncthreads();
        x += y;
        sm[tid] = x;
        __syncthreads();
    }
    if (i < kN) g_row_ptr[i] = x - v;
    if (tid == 1023) g_blk[blockIdx.x] = x;
}

__global__ void k_scan_tops() {
    __shared__ int sm[1024];
    int tid = threadIdx.x;
    int v = (tid < kScanBlocks) ? g_blk[tid] : 0;
    int x = v;
    sm[tid] = x;
    __syncthreads();
    for (int off = 1; off < 1024; off <<= 1) {
        int y = (tid >= off) ? sm[tid - off] : 0;
        __syncthreads();
        x += y;
        sm[tid] = x;
        __syncthreads();
    }
    if (tid < kScanBlocks) g_blk[tid] = x - v;
}

__global__ void k_scan_add_inv(const int* __restrict__ gids) {
    int i = blockIdx.x * blockDim.x + threadIdx.x;
    if (i < kN) {
        int rp = g_row_ptr[i] + g_blk[i >> 10];
        g_row_ptr[i] = rp;
        g_cursor[i]  = rp;
        g_inv_src[i] = rsqrtf((float)max(g_deg_out[i], 1));
        g_inv_dst[i] = rsqrtf((float)max(g_deg_in[i], 1));
        atomicAdd(&g_gcnt[gids[i]], 1);
    }
    if (i == 0) g_row_ptr[kN] = kE;
}

__global__ void k_scatter(const int* __restrict__ src, const int* __restrict__ dst) {
    int e = blockIdx.x * blockDim.x + threadIdx.x;
    if (e >= kE) return;
    int d = dst[e];
    int pos = atomicAdd(&g_cursor[d], 1);
    g_edge_src[pos] = src[e];
}

__global__ void k_wsplit_all(const float* __restrict__ W0, const float* __restrict__ W1,
                             const float* __restrict__ W2) {
    int layer = blockIdx.x >> 6;
    int i = (blockIdx.x & 63) * 256 + threadIdx.x;
    if (i >= kD * kD) return;
    const float* W = (layer == 0) ? W0 : (layer == 1) ? W1 : W2;
    float w = W[i];
    __half h = __float2half_rn(w);
    g_whi[layer * kD * kD + i] = h;
    g_wlo[layer * kD * kD + i] = __float2half_rn(w - __half2float(h));
}

// feats fp32 -> fp16 (into ping buffer A), PRE-SCALED by inv_src[row]
__global__ void k_f2h(const float* __restrict__ x) {
    int i = blockIdx.x * blockDim.x + threadIdx.x;
    if (i >= kN * kD / 4) return;
    int row = i >> 5;
    float s = g_inv_src[row];
    float4 v = reinterpret_cast<const float4*>(x)[i];
    __half2 a = __floats2half2_rn(v.x * s, v.y * s);
    __half2 b = __floats2half2_rn(v.z * s, v.w * s);
    reinterpret_cast<__half2*>(g_h16a)[2 * i + 0] = a;
    reinterpret_cast<__half2*>(g_h16a)[2 * i + 1] = b;
}

// ---------------- FUSED layer: gather (16 nodes/warp) -> smem A -> mma GEMM ----------------
// Hin and Hout are DIFFERENT buffers (ping-pong) to avoid cross-block races.
constexpr int kSA = 136;
constexpr int kTileB = 128 * kSA * 2;            // 34816 bytes
constexpr int kOffA   = 0;
constexpr int kOffBhi = kTileB;
constexpr int kOffBlo = 2 * kTileB;
constexpr int kMmaSmemBytes = 3 * kTileB;        // 104448 -> 2 CTAs/SM

__device__ __forceinline__ void stage_tile(char* smem, int off,
                                           const unsigned short* __restrict__ src,
                                           int row0, int rows, int tid) {
    #pragma unroll
    for (int it = 0; it < 8; ++it) {
        int chunk = tid + it * 256;
        int r = chunk >> 4;
        int c8 = (chunk & 15) << 3;
        uint4 v = make_uint4(0u, 0u, 0u, 0u);
        int gr = row0 + r;
        if (gr < rows) v = *reinterpret_cast<const uint4*>(src + (size_t)gr * 128 + c8);
        *reinterpret_cast<uint4*>(smem + off + (r * kSA + c8) * 2) = v;
    }
}

// EPI=0: write fp16 Hout PRE-SCALED by inv_src[row]; EPI=1: atomicAdd into g_emb
template <int EPI>
__global__ void __launch_bounds__(256, 2)
k_layer(const __half* __restrict__ Hin, __half* __restrict__ Hout,
        const __half* __restrict__ Bhi, const __half* __restrict__ Blo,
        const float* __restrict__ bias, const int* __restrict__ gids, int rows) {
    extern __shared__ char smem[];
    uint32_t sb = smem_u32(smem);
    int tid = threadIdx.x;
    int lane = tid & 31;
    int wid = tid >> 5;
    int row0 = blockIdx.x * 128;

    stage_tile(smem, kOffBhi, reinterpret_cast<const unsigned short*>(Bhi), 0, 128, tid);
    stage_tile(smem, kOffBlo, reinterpret_cast<const unsigned short*>(Blo), 0, 128, tid);

    // gather: each warp aggregates 16 consecutive tile rows directly into smem A (fp16)
    const uint2* H2 = reinterpret_cast<const uint2*>(Hin);
    for (int i = 0; i < 16; ++i) {
        int rloc = wid * 16 + i;
        int node = row0 + rloc;
        float4 acc = make_float4(0.f, 0.f, 0.f, 0.f);
        if (node < rows) {
            int e0 = g_row_ptr[node];
            int e1 = g_row_ptr[node + 1];
            int e = e0;
            for (; e + 7 < e1; e += 8) {
                int s0 = g_edge_src[e + 0];
                int s1 = g_edge_src[e + 1];
                int s2 = g_edge_src[e + 2];
                int s3 = g_edge_src[e + 3];
                int s4 = g_edge_src[e + 4];
                int s5 = g_edge_src[e + 5];
                int s6 = g_edge_src[e + 6];
                int s7 = g_edge_src[e + 7];
                uint2 r0 = H2[(size_t)s0 * 32 + lane];
                uint2 r1 = H2[(size_t)s1 * 32 + lane];
                uint2 r2 = H2[(size_t)s2 * 32 + lane];
                uint2 r3 = H2[(size_t)s3 * 32 + lane];
                uint2 r4 = H2[(size_t)s4 * 32 + lane];
                uint2 r5 = H2[(size_t)s5 * 32 + lane];
                uint2 r6 = H2[(size_t)s6 * 32 + lane];
                uint2 r7 = H2[(size_t)s7 * 32 + lane];
                #define ACC(r) { \
                    float2 a_ = __half22float2(*reinterpret_cast<__half2*>(&(r).x)); \
                    float2 b_ = __half22float2(*reinterpret_cast<__half2*>(&(r).y)); \
                    acc.x += a_.x; acc.y += a_.y; acc.z += b_.x; acc.w += b_.y; }
                ACC(r0) ACC(r1) ACC(r2) ACC(r3) ACC(r4) ACC(r5) ACC(r6) ACC(r7)
            }
            for (; e < e1; ++e) {
                int s = g_edge_src[e];
                uint2 r = H2[(size_t)s * 32 + lane];
                ACC(r)
            }
            #undef ACC
            float wd = g_inv_dst[node];
            acc.x *= wd; acc.y *= wd; acc.z *= wd; acc.w *= wd;
        }
        uint2 o;
        *reinterpret_cast<__half2*>(&o.x) = __floats2half2_rn(acc.x, acc.y);
        *reinterpret_cast<__half2*>(&o.y) = __floats2half2_rn(acc.z, acc.w);
        *reinterpret_cast<uint2*>(smem + kOffA + (rloc * kSA + 4 * lane) * 2) = o;
    }
    __syncthreads();

    // ---- mma GEMM ----
    int wm = wid & 3;
    int wn = wid >> 2;
    int base_m = wm * 32;
    int base_n = wn * 64;

    int l16 = lane & 15;
    int c8  = (lane >> 4) << 3;
    uint32_t a_base = sb + ((base_m + l16) * kSA + c8) * 2;
    uint32_t b_base = sb + (l16 * kSA + base_n + c8) * 2;

    float acc[16][4];
    #pragma unroll
    for (int t = 0; t < 16; ++t)
        #pragma unroll
        for (int j = 0; j < 4; ++j) acc[t][j] = 0.f;

    #pragma unroll
    for (int pass = 0; pass < 2; ++pass) {
        int offB = (pass == 0) ? kOffBhi : kOffBlo;
        #pragma unroll
        for (int ks = 0; ks < 8; ++ks) {
            uint32_t af[2][4];
            ldsm_x4(af[0], a_base + kOffA + 0 * 16 * kSA * 2 + ks * 32);
            ldsm_x4(af[1], a_base + kOffA + 1 * 16 * kSA * 2 + ks * 32);
            uint32_t bf[4][4];
            #pragma unroll
            for (int np = 0; np < 4; ++np)
                ldsm_x4_t(bf[np], b_base + offB + ks * 16 * kSA * 2 + np * 32);
            #pragma unroll
            for (int mt = 0; mt < 2; ++mt)
                #pragma unroll
                for (int nt = 0; nt < 8; ++nt)
                    mma16816h(acc[mt * 8 + nt], af[mt], &bf[nt >> 1][(nt & 1) * 2]);
        }
    }

    #pragma unroll
    for (int mt = 0; mt < 2; ++mt) {
        int r0 = row0 + base_m + mt * 16 + (lane >> 2);
        int r1 = r0 + 8;
        int gid0 = -1, gid1 = -1;
        float sc0 = 0.f, sc1 = 0.f;
        if (EPI == 1) {
            if (r0 < rows) gid0 = gids[r0];
            if (r1 < rows) gid1 = gids[r1];
        } else {
            if (r0 < rows) sc0 = g_inv_src[r0];
            if (r1 < rows) sc1 = g_inv_src[r1];
        }
        #pragma unroll
        for (int nt = 0; nt < 8; ++nt) {
            const float* a = acc[mt * 8 + nt];
            int col = base_n + nt * 8 + ((lane & 3) << 1);
            float2 bb = *reinterpret_cast<const float2*>(&bias[col]);
            float o0x = fmaxf(a[0] + bb.x, 0.f);
            float o0y = fmaxf(a[1] + bb.y, 0.f);
            float o1x = fmaxf(a[2] + bb.x, 0.f);
            float o1y = fmaxf(a[3] + bb.y, 0.f);
            if (EPI == 0) {
                if (r0 < rows)
                    *reinterpret_cast<__half2*>(Hout + (size_t)r0 * 128 + col) =
                        __floats2half2_rn(o0x * sc0, o0y * sc0);
                if (r1 < rows)
                    *reinterpret_cast<__half2*>(Hout + (size_t)r1 * 128 + col) =
                        __floats2half2_rn(o1x * sc1, o1y * sc1);
            } else {
                if (gid0 >= 0) {
                    atomicAdd(g_emb + (size_t)gid0 * 128 + col,     o0x);
                    atomicAdd(g_emb + (size_t)gid0 * 128 + col + 1, o0y);
                }
                if (gid1 >= 0) {
                    atomicAdd(g_emb + (size_t)gid1 * 128 + col,     o1x);
                    atomicAdd(g_emb + (size_t)gid1 * 128 + col + 1, o1y);
                }
            }
        }
    }
}

// ---------------- MLP head (NORM: divide X rows by graph counts) ----------------
template <bool NORM>
__global__ void k_mlp(const float* __restrict__ X, const float* __restrict__ W,
                      const float* __restrict__ b, float* __restrict__ Y,
                      int K, int M) {
    int idx = blockIdx.x * blockDim.x + threadIdx.x;
    int c = idx % M;
    int g0 = (idx / M) * 8;
    if (g0 >= kG) return;
    float acc[8];
    #pragma unroll
    for (int j = 0; j < 8; ++j) acc[j] = 0.f;
    for (int k = 0; k < K; ++k) {
        float w = W[(size_t)k * M + c];
        #pragma unroll
        for (int j = 0; j < 8; ++j)
            acc[j] += X[(size_t)(g0 + j) * K + k] * w;
    }
    float bias = b[c];
    #pragma unroll
    for (int j = 0; j < 8; ++j) {
        float v = acc[j];
        if (NORM) v *= 1.f / (float)max(g_gcnt[g0 + j], 1);
        Y[(size_t)(g0 + j) * M + c] = fmaxf(v + bias, 0.f);
    }
}

__global__ void k_final(const float* __restrict__ X, const float* __restrict__ W,
                        const float* __restrict__ b, float* __restrict__ out) {
    int g = (blockIdx.x * blockDim.x + threadIdx.x) >> 5;
    int lane = threadIdx.x & 31;
    if (g >= kG) return;
    float s = 0.f;
    #pragma unroll
    for (int k = lane; k < 256; k += 32) s += X[(size_t)g * 256 + k] * W[k];
    #pragma unroll
    for (int off = 16; off; off >>= 1) s += __shfl_down_sync(0xffffffffu, s, off);
    if (lane == 0) out[g] = s + b[0];
}

// ---------------- launch ----------------
extern "C" void kernel_launch(void* const* d_in, const int* in_sizes, int n_in,
                              void* d_out, int out_size) {
    const float* feats = (const float*)d_in[0];
    const int*   src   = (const int*)d_in[1];
    const int*   dst   = (const int*)d_in[2];
    const int*   gids  = (const int*)d_in[3];
    const float* W0 = (const float*)d_in[4];  const float* b0 = (const float*)d_in[5];
    const float* W1 = (const float*)d_in[6];  const float* b1 = (const float*)d_in[7];
    const float* W2 = (const float*)d_in[8];  const float* b2 = (const float*)d_in[9];
    const float* Wm0 = (const float*)d_in[10]; const float* bm0 = (const float*)d_in[11];
    const float* Wm1 = (const float*)d_in[12]; const float* bm1 = (const float*)d_in[13];
    const float* Wm2 = (const float*)d_in[14]; const float* bm2 = (const float*)d_in[15];
    float* out = (float*)d_out;

    float *emb, *x1, *x2;
    __half *ha, *hb, *whi, *wlo;
    cudaGetSymbolAddress((void**)&emb,  g_emb);
    cudaGetSymbolAddress((void**)&x1,   g_x1);
    cudaGetSymbolAddress((void**)&x2,   g_x2);
    cudaGetSymbolAddress((void**)&ha,   g_h16a);
    cudaGetSymbolAddress((void**)&hb,   g_h16b);
    cudaGetSymbolAddress((void**)&whi,  g_whi);
    cudaGetSymbolAddress((void**)&wlo,  g_wlo);

    cudaFuncSetAttribute(k_layer<0>, cudaFuncAttributeMaxDynamicSharedMemorySize,
                         kMmaSmemBytes);
    cudaFuncSetAttribute(k_layer<1>, cudaFuncAttributeMaxDynamicSharedMemorySize,
                         kMmaSmemBytes);

    const int T = 256;
    int nBlkN = (kN + T - 1) / T;           // 391
    int nBlkZ = (kG * kD + T - 1) / T;      // 1024
    int nBlkE = (kE + T - 1) / T;           // 6250
    int nBlkTc = (kN + 127) / 128;          // 782
    int nBlkH = (kN * kD / 4 + T - 1) / T;  // 12500

    k_zero<<<nBlkZ, T>>>();
    k_degrees<<<nBlkE, T>>>(src, dst);
    k_scan1<<<kScanBlocks, 1024>>>();
    k_scan_tops<<<1, 1024>>>();
    k_scan_add_inv<<<nBlkN, T>>>(gids);
    k_scatter<<<nBlkE, T>>>(src, dst);
    k_wsplit_all<<<192, T>>>(W0, W1, W2);
    k_f2h<<<nBlkH, T>>>(feats);

    // ping-pong: A -> B -> A -> emb
    k_layer<0><<<nBlkTc, T, kMmaSmemBytes>>>(ha, hb, whi + 0 * kD * kD, wlo + 0 * kD * kD,
                                             b0, gids, kN);
    k_layer<0><<<nBlkTc, T, kMmaSmemBytes>>>(hb, ha, whi + 1 * kD * kD, wlo + 1 * kD * kD,
                                             b1, gids, kN);
    k_layer<1><<<nBlkTc, T, kMmaSmemBytes>>>(ha, nullptr, whi + 2 * kD * kD, wlo + 2 * kD * kD,
                                             b2, gids, kN);

    k_mlp<true><<<(kG / 8) * 512 / T, T>>>(emb, Wm0, bm0, x1, 128, 512);
    k_mlp<false><<<(kG / 8) * 256 / T, T>>>(x1, Wm1, bm1, x2, 512, 256);
    k_final<<<(kG * 32) / T, T>>>(x2, Wm2, bm2, out);
}

// round 12
// speedup vs baseline: 1.3494x; 1.3494x over previous
#include <cuda_runtime.h>
#include <cuda_bf16.h>
#include <cuda_fp16.h>
#include <cstdint>

constexpr int kN = 100000;
constexpr int kE = 1600000;
constexpr int kG = 2048;
constexpr int kD = 128;
constexpr int kScanBlocks = (kN + 1023) / 1024; // 98

// ---------------- scratch (no allocations allowed) ----------------
__device__ __half g_h16[kN * kD];            // pre-scaled rows h, fp16
__device__ __half g_m16[kN * kD];            // gathered m, fp16
__device__ __half g_whi[3 * kD * kD];        // W fp16 hi, [K][N]
__device__ __half g_wlo[3 * kD * kD];        // W fp16 lo, [K][N]
__device__ float g_inv_src[kN];
__device__ float g_inv_dst[kN];
__device__ int   g_deg_out[kN];
__device__ int   g_deg_in[kN];
__device__ int   g_row_ptr[kN + 1];
__device__ int   g_cursor[kN];
__device__ int   g_edge_src[kE];
__device__ int   g_blk[kScanBlocks];
__device__ float g_emb[kG * kD];
__device__ int   g_gcnt[kG];
__device__ float g_x1[kG * 512];
__device__ float g_x2[kG * 256];

// ---------------- mma / ldmatrix helpers (base ISA, sm_80+) ----------------
__device__ __forceinline__ uint32_t smem_u32(const void* p) {
    uint32_t a;
    asm("{ .reg .u64 t; cvta.to.shared.u64 t, %1; cvt.u32.u64 %0, t; }" : "=r"(a) : "l"(p));
    return a;
}
__device__ __forceinline__ void ldsm_x4(uint32_t* r, uint32_t addr) {
    asm volatile("ldmatrix.sync.aligned.m8n8.x4.shared.b16 {%0,%1,%2,%3}, [%4];"
                 : "=r"(r[0]), "=r"(r[1]), "=r"(r[2]), "=r"(r[3]) : "r"(addr));
}
__device__ __forceinline__ void ldsm_x4_t(uint32_t* r, uint32_t addr) {
    asm volatile("ldmatrix.sync.aligned.m8n8.x4.trans.shared.b16 {%0,%1,%2,%3}, [%4];"
                 : "=r"(r[0]), "=r"(r[1]), "=r"(r[2]), "=r"(r[3]) : "r"(addr));
}
__device__ __forceinline__ void mma16816h(float* d, const uint32_t* a, const uint32_t* b) {
    asm volatile(
        "mma.sync.aligned.m16n8k16.row.col.f32.f16.f16.f32 "
        "{%0,%1,%2,%3}, {%4,%5,%6,%7}, {%8,%9}, {%0,%1,%2,%3};"
        : "+f"(d[0]), "+f"(d[1]), "+f"(d[2]), "+f"(d[3])
        : "r"(a[0]), "r"(a[1]), "r"(a[2]), "r"(a[3]), "r"(b[0]), "r"(b[1]));
}

// ---------------- setup kernels (R8 structure — measured best) ----------------
__global__ void k_zero() {
    int i = blockIdx.x * blockDim.x + threadIdx.x;
    if (i < kN) { g_deg_out[i] = 0; g_deg_in[i] = 0; }
    if (i < kG * kD) g_emb[i] = 0.f;
    if (i < kG) g_gcnt[i] = 0;
}

__global__ void k_degrees(const int* __restrict__ src, const int* __restrict__ dst) {
    int e = blockIdx.x * blockDim.x + threadIdx.x;
    if (e >= kE) return;
    atomicAdd(&g_deg_out[src[e]], 1);
    atomicAdd(&g_deg_in[dst[e]], 1);
}

__global__ void k_scan1() {
    __shared__ int sm[1024];
    int tid = threadIdx.x;
    int i = blockIdx.x * 1024 + tid;
    int v = (i < kN) ? g_deg_in[i] : 0;
    int x = v;
    sm[tid] = x;
    __syncthreads();
    for (int off = 1; off < 1024; off <<= 1) {
        int y = (tid >= off) ? sm[tid - off] : 0;
        __syncthreads();
        x += y;
        sm[tid] = x;
        __syncthreads();
    }
    if (i < kN) g_row_ptr[i] = x - v;
    if (tid == 1023) g_blk[blockIdx.x] = x;
}

__global__ void k_scan_tops() {
    __shared__ int sm[1024];
    int tid = threadIdx.x;
    int v = (tid < kScanBlocks) ? g_blk[tid] : 0;
    int x = v;
    sm[tid] = x;
    __syncthreads();
    for (int off = 1; off < 1024; off <<= 1) {
        int y = (tid >= off) ? sm[tid - off] : 0;
        __syncthreads();
        x += y;
        sm[tid] = x;
        __syncthreads();
    }
    if (tid < kScanBlocks) g_blk[tid] = x - v;
}

__global__ void k_scan_add_inv(const int* __restrict__ gids) {
    int i = blockIdx.x * blockDim.x + threadIdx.x;
    if (i < kN) {
        int rp = g_row_ptr[i] + g_blk[i >> 10];
        g_row_ptr[i] = rp;
        g_cursor[i]  = rp;
        g_inv_src[i] = rsqrtf((float)max(g_deg_out[i], 1));
        g_inv_dst[i] = rsqrtf((float)max(g_deg_in[i], 1));
        atomicAdd(&g_gcnt[gids[i]], 1);
    }
    if (i == 0) g_row_ptr[kN] = kE;
}

__global__ void k_scatter(const int* __restrict__ src, const int* __restrict__ dst) {
    int e = blockIdx.x * blockDim.x + threadIdx.x;
    if (e >= kE) return;
    int d = dst[e];
    int pos = atomicAdd(&g_cursor[d], 1);
    g_edge_src[pos] = src[e];
}

__global__ void k_wsplit_all(const float* __restrict__ W0, const float* __restrict__ W1,
                             const float* __restrict__ W2) {
    int layer = blockIdx.x >> 6;
    int i = (blockIdx.x & 63) * 256 + threadIdx.x;
    if (i >= kD * kD) return;
    const float* W = (layer == 0) ? W0 : (layer == 1) ? W1 : W2;
    float w = W[i];
    __half h = __float2half_rn(w);
    g_whi[layer * kD * kD + i] = h;
    g_wlo[layer * kD * kD + i] = __float2half_rn(w - __half2float(h));
}

// feats fp32 -> fp16, PRE-SCALED by inv_src[row]
__global__ void k_f2h(const float* __restrict__ x) {
    int i = blockIdx.x * blockDim.x + threadIdx.x;
    if (i >= kN * kD / 4) return;
    int row = i >> 5;
    float s = g_inv_src[row];
    float4 v = reinterpret_cast<const float4*>(x)[i];
    __half2 a = __floats2half2_rn(v.x * s, v.y * s);
    __half2 b = __floats2half2_rn(v.z * s, v.w * s);
    reinterpret_cast<__half2*>(g_h16)[2 * i + 0] = a;
    reinterpret_cast<__half2*>(g_h16)[2 * i + 1] = b;
}

// ---------------- GCN aggregation: one warp per PAIR of nodes -> fp16 m ----------------
// Two independent id->row load chains interleaved for 2x memory-level parallelism.
#define ACC(dst, r) { \
    float2 a_ = __half22float2(*reinterpret_cast<__half2*>(&(r).x)); \
    float2 b_ = __half22float2(*reinterpret_cast<__half2*>(&(r).y)); \
    dst.x += a_.x; dst.y += a_.y; dst.z += b_.x; dst.w += b_.y; }

__global__ void k_gather() {
    int wp = (blockIdx.x * blockDim.x + threadIdx.x) >> 5;
    int lane = threadIdx.x & 31;
    int n0 = wp * 2;
    if (n0 >= kN) return;
    int n1 = n0 + 1;   // kN even -> always valid
    const uint2* H2 = reinterpret_cast<const uint2*>(g_h16);

    int a  = g_row_ptr[n0];
    int ea = g_row_ptr[n0 + 1];
    int b  = a == ea ? 0 : ea;       // n1 list starts at ea (contiguous CSR)
    b = g_row_ptr[n1];
    int eb = g_row_ptr[n1 + 1];

    float4 accA = make_float4(0.f, 0.f, 0.f, 0.f);
    float4 accB = make_float4(0.f, 0.f, 0.f, 0.f);

    // dual phase: 4+4 edges, 8 independent row loads in flight across 2 chains
    while (a + 3 < ea && b + 3 < eb) {
        int sa0 = g_edge_src[a + 0];
        int sa1 = g_edge_src[a + 1];
        int sa2 = g_edge_src[a + 2];
        int sa3 = g_edge_src[a + 3];
        int sb0 = g_edge_src[b + 0];
        int sb1 = g_edge_src[b + 1];
        int sb2 = g_edge_src[b + 2];
        int sb3 = g_edge_src[b + 3];
        uint2 ra0 = H2[(size_t)sa0 * 32 + lane];
        uint2 ra1 = H2[(size_t)sa1 * 32 + lane];
        uint2 ra2 = H2[(size_t)sa2 * 32 + lane];
        uint2 ra3 = H2[(size_t)sa3 * 32 + lane];
        uint2 rb0 = H2[(size_t)sb0 * 32 + lane];
        uint2 rb1 = H2[(size_t)sb1 * 32 + lane];
        uint2 rb2 = H2[(size_t)sb2 * 32 + lane];
        uint2 rb3 = H2[(size_t)sb3 * 32 + lane];
        ACC(accA, ra0) ACC(accA, ra1) ACC(accA, ra2) ACC(accA, ra3)
        ACC(accB, rb0) ACC(accB, rb1) ACC(accB, rb2) ACC(accB, rb3)
        a += 4; b += 4;
    }
    // drain A (4-unroll + scalar)
    for (; a + 3 < ea; a += 4) {
        int s0 = g_edge_src[a + 0];
        int s1 = g_edge_src[a + 1];
        int s2 = g_edge_src[a + 2];
        int s3 = g_edge_src[a + 3];
        uint2 r0 = H2[(size_t)s0 * 32 + lane];
        uint2 r1 = H2[(size_t)s1 * 32 + lane];
        uint2 r2 = H2[(size_t)s2 * 32 + lane];
        uint2 r3 = H2[(size_t)s3 * 32 + lane];
        ACC(accA, r0) ACC(accA, r1) ACC(accA, r2) ACC(accA, r3)
    }
    for (; a < ea; ++a) {
        int s = g_edge_src[a];
        uint2 r = H2[(size_t)s * 32 + lane];
        ACC(accA, r)
    }
    // drain B
    for (; b + 3 < eb; b += 4) {
        int s0 = g_edge_src[b + 0];
        int s1 = g_edge_src[b + 1];
        int s2 = g_edge_src[b + 2];
        int s3 = g_edge_src[b + 3];
        uint2 r0 = H2[(size_t)s0 * 32 + lane];
        uint2 r1 = H2[(size_t)s1 * 32 + lane];
        uint2 r2 = H2[(size_t)s2 * 32 + lane];
        uint2 r3 = H2[(size_t)s3 * 32 + lane];
        ACC(accB, r0) ACC(accB, r1) ACC(accB, r2) ACC(accB, r3)
    }
    for (; b < eb; ++b) {
        int s = g_edge_src[b];
        uint2 r = H2[(size_t)s * 32 + lane];
        ACC(accB, r)
    }

    float wd0 = g_inv_dst[n0];
    float wd1 = g_inv_dst[n1];
    uint2 o0, o1;
    *reinterpret_cast<__half2*>(&o0.x) = __floats2half2_rn(accA.x * wd0, accA.y * wd0);
    *reinterpret_cast<__half2*>(&o0.y) = __floats2half2_rn(accA.z * wd0, accA.w * wd0);
    *reinterpret_cast<__half2*>(&o1.x) = __floats2half2_rn(accB.x * wd1, accB.y * wd1);
    *reinterpret_cast<__half2*>(&o1.y) = __floats2half2_rn(accB.z * wd1, accB.w * wd1);
    reinterpret_cast<uint2*>(g_m16)[(size_t)n0 * 32 + lane] = o0;
    reinterpret_cast<uint2*>(g_m16)[(size_t)n1 * 32 + lane] = o1;
}
#undef ACC

// ---------------- mma.sync GEMM: [128,128] tile, fp16 A x (fp16 hi+lo W), fp32 acc ----------------
constexpr int kSA = 136;
constexpr int kTileB = 128 * kSA * 2;            // 34816 bytes
constexpr int kOffA   = 0;
constexpr int kOffBhi = kTileB;
constexpr int kOffBlo = 2 * kTileB;
constexpr int kMmaSmemBytes = 3 * kTileB;        // 104448 -> 2 CTAs/SM

__device__ __forceinline__ void stage_tile(char* smem, int off,
                                           const unsigned short* __restrict__ src,
                                           int row0, int rows, int tid) {
    #pragma unroll
    for (int it = 0; it < 8; ++it) {
        int chunk = tid + it * 256;
        int r = chunk >> 4;
        int c8 = (chunk & 15) << 3;
        uint4 v = make_uint4(0u, 0u, 0u, 0u);
        int gr = row0 + r;
        if (gr < rows) v = *reinterpret_cast<const uint4*>(src + (size_t)gr * 128 + c8);
        *reinterpret_cast<uint4*>(smem + off + (r * kSA + c8) * 2) = v;
    }
}

// EPI=0: write fp16 h PRE-SCALED by inv_src[row]; EPI=1: atomicAdd into g_emb
template <int EPI>
__global__ void __launch_bounds__(256, 2)
k_gemm_mma(const __half* __restrict__ Bhi, const __half* __restrict__ Blo,
           const float* __restrict__ bias, const int* __restrict__ gids, int rows) {
    extern __shared__ char smem[];
    uint32_t sb = smem_u32(smem);
    int tid = threadIdx.x;
    int lane = tid & 31;
    int wid = tid >> 5;
    int row0 = blockIdx.x * 128;

    stage_tile(smem, kOffA, reinterpret_cast<const unsigned short*>(g_m16), row0, rows, tid);
    stage_tile(smem, kOffBhi, reinterpret_cast<const unsigned short*>(Bhi), 0, 128, tid);
    stage_tile(smem, kOffBlo, reinterpret_cast<const unsigned short*>(Blo), 0, 128, tid);
    __syncthreads();

    int wm = wid & 3;
    int wn = wid >> 2;
    int base_m = wm * 32;
    int base_n = wn * 64;

    int l16 = lane & 15;
    int c8  = (lane >> 4) << 3;
    uint32_t a_base = sb + ((base_m + l16) * kSA + c8) * 2;
    uint32_t b_base = sb + (l16 * kSA + base_n + c8) * 2;

    float acc[16][4];
    #pragma unroll
    for (int t = 0; t < 16; ++t)
        #pragma unroll
        for (int j = 0; j < 4; ++j) acc[t][j] = 0.f;

    #pragma unroll
    for (int pass = 0; pass < 2; ++pass) {
        int offB = (pass == 0) ? kOffBhi : kOffBlo;
        #pragma unroll
        for (int ks = 0; ks < 8; ++ks) {
            uint32_t af[2][4];
            ldsm_x4(af[0], a_base + kOffA + 0 * 16 * kSA * 2 + ks * 32);
            ldsm_x4(af[1], a_base + kOffA + 1 * 16 * kSA * 2 + ks * 32);
            uint32_t bf[4][4];
            #pragma unroll
            for (int np = 0; np < 4; ++np)
                ldsm_x4_t(bf[np], b_base + offB + ks * 16 * kSA * 2 + np * 32);
            #pragma unroll
            for (int mt = 0; mt < 2; ++mt)
                #pragma unroll
                for (int nt = 0; nt < 8; ++nt)
                    mma16816h(acc[mt * 8 + nt], af[mt], &bf[nt >> 1][(nt & 1) * 2]);
        }
    }

    #pragma unroll
    for (int mt = 0; mt < 2; ++mt) {
        int r0 = row0 + base_m + mt * 16 + (lane >> 2);
        int r1 = r0 + 8;
        int gid0 = -1, gid1 = -1;
        float sc0 = 0.f, sc1 = 0.f;
        if (EPI == 1) {
            if (r0 < rows) gid0 = gids[r0];
            if (r1 < rows) gid1 = gids[r1];
        } else {
            if (r0 < rows) sc0 = g_inv_src[r0];
            if (r1 < rows) sc1 = g_inv_src[r1];
        }
        #pragma unroll
        for (int nt = 0; nt < 8; ++nt) {
            const float* a = acc[mt * 8 + nt];
            int col = base_n + nt * 8 + ((lane & 3) << 1);
            float2 bb = *reinterpret_cast<const float2*>(&bias[col]);
            float o0x = fmaxf(a[0] + bb.x, 0.f);
            float o0y = fmaxf(a[1] + bb.y, 0.f);
            float o1x = fmaxf(a[2] + bb.x, 0.f);
            float o1y = fmaxf(a[3] + bb.y, 0.f);
            if (EPI == 0) {
                if (r0 < rows)
                    *reinterpret_cast<__half2*>(g_h16 + (size_t)r0 * 128 + col) =
                        __floats2half2_rn(o0x * sc0, o0y * sc0);
                if (r1 < rows)
                    *reinterpret_cast<__half2*>(g_h16 + (size_t)r1 * 128 + col) =
                        __floats2half2_rn(o1x * sc1, o1y * sc1);
            } else {
                if (gid0 >= 0) {
                    atomicAdd(g_emb + (size_t)gid0 * 128 + col,     o0x);
                    atomicAdd(g_emb + (size_t)gid0 * 128 + col + 1, o0y);
                }
                if (gid1 >= 0) {
                    atomicAdd(g_emb + (size_t)gid1 * 128 + col,     o1x);
                    atomicAdd(g_emb + (size_t)gid1 * 128 + col + 1, o1y);
                }
            }
        }
    }
}

// ---------------- MLP head (NORM: divide X rows by graph counts) ----------------
template <bool NORM>
__global__ void k_mlp(const float* __restrict__ X, const float* __restrict__ W,
                      const float* __restrict__ b, float* __restrict__ Y,
                      int K, int M) {
    int idx = blockIdx.x * blockDim.x + threadIdx.x;
    int c = idx % M;
    int g0 = (idx / M) * 8;
    if (g0 >= kG) return;
    float acc[8];
    #pragma unroll
    for (int j = 0; j < 8; ++j) acc[j] = 0.f;
    for (int k = 0; k < K; ++k) {
        float w = W[(size_t)k * M + c];
        #pragma unroll
        for (int j = 0; j < 8; ++j)
            acc[j] += X[(size_t)(g0 + j) * K + k] * w;
    }
    float bias = b[c];
    #pragma unroll
    for (int j = 0; j < 8; ++j) {
        float v = acc[j];
        if (NORM) v *= 1.f / (float)max(g_gcnt[g0 + j], 1);
        Y[(size_t)(g0 + j) * M + c] = fmaxf(v + bias, 0.f);
    }
}

__global__ void k_final(const float* __restrict__ X, const float* __restrict__ W,
                        const float* __restrict__ b, float* __restrict__ out) {
    int g = (blockIdx.x * blockDim.x + threadIdx.x) >> 5;
    int lane = threadIdx.x & 31;
    if (g >= kG) return;
    float s = 0.f;
    #pragma unroll
    for (int k = lane; k < 256; k += 32) s += X[(size_t)g * 256 + k] * W[k];
    #pragma unroll
    for (int off = 16; off; off >>= 1) s += __shfl_down_sync(0xffffffffu, s, off);
    if (lane == 0) out[g] = s + b[0];
}

// ---------------- launch ----------------
extern "C" void kernel_launch(void* const* d_in, const int* in_sizes, int n_in,
                              void* d_out, int out_size) {
    const float* feats = (const float*)d_in[0];
    const int*   src   = (const int*)d_in[1];
    const int*   dst   = (const int*)d_in[2];
    const int*   gids  = (const int*)d_in[3];
    const float* W0 = (const float*)d_in[4];  const float* b0 = (const float*)d_in[5];
    const float* W1 = (const float*)d_in[6];  const float* b1 = (const float*)d_in[7];
    const float* W2 = (const float*)d_in[8];  const float* b2 = (const float*)d_in[9];
    const float* Wm0 = (const float*)d_in[10]; const float* bm0 = (const float*)d_in[11];
    const float* Wm1 = (const float*)d_in[12]; const float* bm1 = (const float*)d_in[13];
    const float* Wm2 = (const float*)d_in[14]; const float* bm2 = (const float*)d_in[15];
    float* out = (float*)d_out;

    float *emb, *x1, *x2;
    __half *whi, *wlo;
    cudaGetSymbolAddress((void**)&emb,  g_emb);
    cudaGetSymbolAddress((void**)&x1,   g_x1);
    cudaGetSymbolAddress((void**)&x2,   g_x2);
    cudaGetSymbolAddress((void**)&whi,  g_whi);
    cudaGetSymbolAddress((void**)&wlo,  g_wlo);

    cudaFuncSetAttribute(k_gemm_mma<0>, cudaFuncAttributeMaxDynamicSharedMemorySize,
                         kMmaSmemBytes);
    cudaFuncSetAttribute(k_gemm_mma<1>, cudaFuncAttributeMaxDynamicSharedMemorySize,
                         kMmaSmemBytes);

    const int T = 256;
    int nBlkN = (kN + T - 1) / T;                 // 391
    int nBlkZ = (kG * kD + T - 1) / T;            // 1024
    int nBlkE = (kE + T - 1) / T;                 // 6250
    int nBlkPair = ((kN / 2) * 32 + T - 1) / T;   // 6250 (warp per node-pair)
    int nBlkTc = (kN + 127) / 128;                // 782
    int nBlkH = (kN * kD / 4 + T - 1) / T;        // 12500

    k_zero<<<nBlkZ, T>>>();
    k_degrees<<<nBlkE, T>>>(src, dst);
    k_scan1<<<kScanBlocks, 1024>>>();
    k_scan_tops<<<1, 1024>>>();
    k_scan_add_inv<<<nBlkN, T>>>(gids);
    k_scatter<<<nBlkE, T>>>(src, dst);
    k_wsplit_all<<<192, T>>>(W0, W1, W2);
    k_f2h<<<nBlkH, T>>>(feats);

    k_gather<<<nBlkPair, T>>>();
    k_gemm_mma<0><<<nBlkTc, T, kMmaSmemBytes>>>(whi + 0 * kD * kD, wlo + 0 * kD * kD,
                                                b0, gids, kN);
    k_gather<<<nBlkPair, T>>>();
    k_gemm_mma<0><<<nBlkTc, T, kMmaSmemBytes>>>(whi + 1 * kD * kD, wlo + 1 * kD * kD,
                                                b1, gids, kN);
    k_gather<<<nBlkPair, T>>>();
    k_gemm_mma<1><<<nBlkTc, T, kMmaSmemBytes>>>(whi + 2 * kD * kD, wlo + 2 * kD * kD,
                                                b2, gids, kN);

    k_mlp<true><<<(kG / 8) * 512 / T, T>>>(emb, Wm0, bm0, x1, 128, 512);
    k_mlp<false><<<(kG / 8) * 256 / T, T>>>(x1, Wm1, bm1, x2, 512, 256);
    k_final<<<(kG * 32) / T, T>>>(x2, Wm2, bm2, out);
}

// round 13
// speedup vs baseline: 1.3628x; 1.0099x over previous
#include <cuda_runtime.h>
#include <cuda_bf16.h>
#include <cuda_fp16.h>
#include <cstdint>

constexpr int kN = 100000;
constexpr int kE = 1600000;
constexpr int kG = 2048;
constexpr int kD = 128;
constexpr int kScanBlocks = (kN + 1023) / 1024; // 98
constexpr int kBlkE = (kE + 255) / 256;          // 6250
constexpr int kBlkH = (kN * kD / 4 + 255) / 256; // 12500
constexpr int kBlkZ = (kG * kD + 255) / 256;     // 1024

// ---------------- scratch (no allocations allowed) ----------------
__device__ __half g_h16[kN * kD];            // pre-scaled rows h, fp16
__device__ __half g_m16[kN * kD];            // gathered m, fp16
__device__ __half g_whi[3 * kD * kD];        // W fp16 hi, [K][N]
__device__ __half g_wlo[3 * kD * kD];        // W fp16 lo, [K][N]
__device__ float g_inv_src[kN];
__device__ float g_inv_dst[kN];
__device__ int   g_deg_out[kN];
__device__ int   g_deg_in[kN];
__device__ int   g_row_ptr[kN + 1];
__device__ int   g_cursor[kN];
__device__ int   g_edge_src[kE];
__device__ int   g_blk[kScanBlocks];
__device__ float g_emb[kG * kD];
__device__ int   g_gcnt[kG];
__device__ float g_x1[kG * 512];
__device__ float g_x2[kG * 256];

// ---------------- mma / ldmatrix helpers (base ISA, sm_80+) ----------------
__device__ __forceinline__ uint32_t smem_u32(const void* p) {
    uint32_t a;
    asm("{ .reg .u64 t; cvta.to.shared.u64 t, %1; cvt.u32.u64 %0, t; }" : "=r"(a) : "l"(p));
    return a;
}
__device__ __forceinline__ void ldsm_x4(uint32_t* r, uint32_t addr) {
    asm volatile("ldmatrix.sync.aligned.m8n8.x4.shared.b16 {%0,%1,%2,%3}, [%4];"
                 : "=r"(r[0]), "=r"(r[1]), "=r"(r[2]), "=r"(r[3]) : "r"(addr));
}
__device__ __forceinline__ void ldsm_x4_t(uint32_t* r, uint32_t addr) {
    asm volatile("ldmatrix.sync.aligned.m8n8.x4.trans.shared.b16 {%0,%1,%2,%3}, [%4];"
                 : "=r"(r[0]), "=r"(r[1]), "=r"(r[2]), "=r"(r[3]) : "r"(addr));
}
__device__ __forceinline__ void mma16816h(float* d, const uint32_t* a, const uint32_t* b) {
    asm volatile(
        "mma.sync.aligned.m16n8k16.row.col.f32.f16.f16.f32 "
        "{%0,%1,%2,%3}, {%4,%5,%6,%7}, {%8,%9}, {%0,%1,%2,%3};"
        : "+f"(d[0]), "+f"(d[1]), "+f"(d[2]), "+f"(d[3])
        : "r"(a[0]), "r"(a[1]), "r"(a[2]), "r"(a[3]), "r"(b[0]), "r"(b[1]));
}

// ---------------- setup kernels ----------------
// zero deg/emb/gcnt + weight split fused (all independent of edge inputs)
__global__ void k_zero_wsplit(const float* __restrict__ W0, const float* __restrict__ W1,
                              const float* __restrict__ W2) {
    if (blockIdx.x < kBlkZ) {
        int i = blockIdx.x * 256 + threadIdx.x;
        if (i < kN) { g_deg_out[i] = 0; g_deg_in[i] = 0; }
        if (i < kG * kD) g_emb[i] = 0.f;
        if (i < kG) g_gcnt[i] = 0;
    } else {
        int b = blockIdx.x - kBlkZ;          // 0..191
        int layer = b >> 6;
        int i = (b & 63) * 256 + threadIdx.x;
        if (i >= kD * kD) return;
        const float* W = (layer == 0) ? W0 : (layer == 1) ? W1 : W2;
        float w = W[i];
        __half h = __float2half_rn(w);
        g_whi[layer * kD * kD + i] = h;
        g_wlo[layer * kD * kD + i] = __float2half_rn(w - __half2float(h));
    }
}

__global__ void k_degrees(const int* __restrict__ src, const int* __restrict__ dst) {
    int e = blockIdx.x * blockDim.x + threadIdx.x;
    if (e >= kE) return;
    atomicAdd(&g_deg_out[src[e]], 1);
    atomicAdd(&g_deg_in[dst[e]], 1);
}

__global__ void k_scan1() {
    __shared__ int sm[1024];
    int tid = threadIdx.x;
    int i = blockIdx.x * 1024 + tid;
    int v = (i < kN) ? g_deg_in[i] : 0;
    int x = v;
    sm[tid] = x;
    __syncthreads();
    for (int off = 1; off < 1024; off <<= 1) {
        int y = (tid >= off) ? sm[tid - off] : 0;
        __syncthreads();
        x += y;
        sm[tid] = x;
        __syncthreads();
    }
    if (i < kN) g_row_ptr[i] = x - v;
    if (tid == 1023) g_blk[blockIdx.x] = x;
}

// scan finalize (per-block redundant tops reduce) + inv norms + graph counts
__global__ void k_scan_add_inv(const int* __restrict__ gids) {
    __shared__ int red[256];
    int tid = threadIdx.x;
    int chunk = blockIdx.x >> 2;   // = i >> 10, constant across this 256-thread block
    int v = (tid < chunk) ? g_blk[tid] : 0;   // chunk <= 97 < 256
    red[tid] = v;
    __syncthreads();
    #pragma unroll
    for (int s = 128; s; s >>= 1) {
        if (tid < s) red[tid] += red[tid + s];
        __syncthreads();
    }
    int pref = red[0];

    int i = blockIdx.x * 256 + tid;
    if (i < kN) {
        int rp = g_row_ptr[i] + pref;
        g_row_ptr[i] = rp;
        g_cursor[i]  = rp;
        g_inv_src[i] = rsqrtf((float)max(g_deg_out[i], 1));
        g_inv_dst[i] = rsqrtf((float)max(g_deg_in[i], 1));
        atomicAdd(&g_gcnt[gids[i]], 1);
    }
    if (i == 0) g_row_ptr[kN] = kE;
}

// scatter into CSR + (fused) feats fp32 -> fp16 pre-scaled by inv_src
__global__ void k_scatter_f2h(const int* __restrict__ src, const int* __restrict__ dst,
                              const float* __restrict__ feats) {
    if (blockIdx.x < kBlkE) {
        int e = blockIdx.x * 256 + threadIdx.x;
        if (e >= kE) return;
        int d = dst[e];
        int pos = atomicAdd(&g_cursor[d], 1);
        g_edge_src[pos] = src[e];
    } else {
        int i = (blockIdx.x - kBlkE) * 256 + threadIdx.x;
        if (i >= kN * kD / 4) return;
        int row = i >> 5;
        float s = g_inv_src[row];
        float4 v = reinterpret_cast<const float4*>(feats)[i];
        __half2 a = __floats2half2_rn(v.x * s, v.y * s);
        __half2 b = __floats2half2_rn(v.z * s, v.w * s);
        reinterpret_cast<__half2*>(g_h16)[2 * i + 0] = a;
        reinterpret_cast<__half2*>(g_h16)[2 * i + 1] = b;
    }
}

// ---------------- GCN aggregation: one warp per dst node -> fp16 m (R8 version) ----------------
__global__ void k_gather() {
    int w = (blockIdx.x * blockDim.x + threadIdx.x) >> 5;
    int lane = threadIdx.x & 31;
    if (w >= kN) return;
    int e0 = g_row_ptr[w];
    int e1 = g_row_ptr[w + 1];
    const uint2* H2 = reinterpret_cast<const uint2*>(g_h16);
    float4 acc = make_float4(0.f, 0.f, 0.f, 0.f);
    int e = e0;
    for (; e + 7 < e1; e += 8) {
        int s0 = g_edge_src[e + 0];
        int s1 = g_edge_src[e + 1];
        int s2 = g_edge_src[e + 2];
        int s3 = g_edge_src[e + 3];
        int s4 = g_edge_src[e + 4];
        int s5 = g_edge_src[e + 5];
        int s6 = g_edge_src[e + 6];
        int s7 = g_edge_src[e + 7];
        uint2 r0 = H2[(size_t)s0 * 32 + lane];
        uint2 r1 = H2[(size_t)s1 * 32 + lane];
        uint2 r2 = H2[(size_t)s2 * 32 + lane];
        uint2 r3 = H2[(size_t)s3 * 32 + lane];
        uint2 r4 = H2[(size_t)s4 * 32 + lane];
        uint2 r5 = H2[(size_t)s5 * 32 + lane];
        uint2 r6 = H2[(size_t)s6 * 32 + lane];
        uint2 r7 = H2[(size_t)s7 * 32 + lane];
        #define ACC(r) { \
            float2 a_ = __half22float2(*reinterpret_cast<__half2*>(&(r).x)); \
            float2 b_ = __half22float2(*reinterpret_cast<__half2*>(&(r).y)); \
            acc.x += a_.x; acc.y += a_.y; acc.z += b_.x; acc.w += b_.y; }
        ACC(r0) ACC(r1) ACC(r2) ACC(r3) ACC(r4) ACC(r5) ACC(r6) ACC(r7)
    }
    for (; e < e1; ++e) {
        int s = g_edge_src[e];
        uint2 r = H2[(size_t)s * 32 + lane];
        ACC(r)
    }
    #undef ACC
    float wd = g_inv_dst[w];
    uint2 o;
    *reinterpret_cast<__half2*>(&o.x) = __floats2half2_rn(acc.x * wd, acc.y * wd);
    *reinterpret_cast<__half2*>(&o.y) = __floats2half2_rn(acc.z * wd, acc.w * wd);
    reinterpret_cast<uint2*>(g_m16)[(size_t)w * 32 + lane] = o;
}

// ---------------- mma.sync GEMM: [128,128] tile, fp16 A x (fp16 hi+lo W), fp32 acc ----------------
constexpr int kSA = 136;
constexpr int kTileB = 128 * kSA * 2;            // 34816 bytes
constexpr int kOffA   = 0;
constexpr int kOffBhi = kTileB;
constexpr int kOffBlo = 2 * kTileB;
constexpr int kMmaSmemBytes = 3 * kTileB;        // 104448 -> 2 CTAs/SM

__device__ __forceinline__ void stage_tile(char* smem, int off,
                                           const unsigned short* __restrict__ src,
                                           int row0, int rows, int tid) {
    #pragma unroll
    for (int it = 0; it < 8; ++it) {
        int chunk = tid + it * 256;
        int r = chunk >> 4;
        int c8 = (chunk & 15) << 3;
        uint4 v = make_uint4(0u, 0u, 0u, 0u);
        int gr = row0 + r;
        if (gr < rows) v = *reinterpret_cast<const uint4*>(src + (size_t)gr * 128 + c8);
        *reinterpret_cast<uint4*>(smem + off + (r * kSA + c8) * 2) = v;
    }
}

// EPI=0: write fp16 h PRE-SCALED by inv_src[row]; EPI=1: atomicAdd into g_emb
template <int EPI>
__global__ void __launch_bounds__(256, 2)
k_gemm_mma(const __half* __restrict__ Bhi, const __half* __restrict__ Blo,
           const float* __restrict__ bias, const int* __restrict__ gids, int rows) {
    extern __shared__ char smem[];
    uint32_t sb = smem_u32(smem);
    int tid = threadIdx.x;
    int lane = tid & 31;
    int wid = tid >> 5;
    int row0 = blockIdx.x * 128;

    stage_tile(smem, kOffA, reinterpret_cast<const unsigned short*>(g_m16), row0, rows, tid);
    stage_tile(smem, kOffBhi, reinterpret_cast<const unsigned short*>(Bhi), 0, 128, tid);
    stage_tile(smem, kOffBlo, reinterpret_cast<const unsigned short*>(Blo), 0, 128, tid);
    __syncthreads();

    int wm = wid & 3;
    int wn = wid >> 2;
    int base_m = wm * 32;
    int base_n = wn * 64;

    int l16 = lane & 15;
    int c8  = (lane >> 4) << 3;
    uint32_t a_base = sb + ((base_m + l16) * kSA + c8) * 2;
    uint32_t b_base = sb + (l16 * kSA + base_n + c8) * 2;

    float acc[16][4];
    #pragma unroll
    for (int t = 0; t < 16; ++t)
        #pragma unroll
        for (int j = 0; j < 4; ++j) acc[t][j] = 0.f;

    #pragma unroll
    for (int pass = 0; pass < 2; ++pass) {
        int offB = (pass == 0) ? kOffBhi : kOffBlo;
        #pragma unroll
        for (int ks = 0; ks < 8; ++ks) {
            uint32_t af[2][4];
            ldsm_x4(af[0], a_base + kOffA + 0 * 16 * kSA * 2 + ks * 32);
            ldsm_x4(af[1], a_base + kOffA + 1 * 16 * kSA * 2 + ks * 32);
            uint32_t bf[4][4];
            #pragma unroll
            for (int np = 0; np < 4; ++np)
                ldsm_x4_t(bf[np], b_base + offB + ks * 16 * kSA * 2 + np * 32);
            #pragma unroll
            for (int mt = 0; mt < 2; ++mt)
                #pragma unroll
                for (int nt = 0; nt < 8; ++nt)
                    mma16816h(acc[mt * 8 + nt], af[mt], &bf[nt >> 1][(nt & 1) * 2]);
        }
    }

    #pragma unroll
    for (int mt = 0; mt < 2; ++mt) {
        int r0 = row0 + base_m + mt * 16 + (lane >> 2);
        int r1 = r0 + 8;
        int gid0 = -1, gid1 = -1;
        float sc0 = 0.f, sc1 = 0.f;
        if (EPI == 1) {
            if (r0 < rows) gid0 = gids[r0];
            if (r1 < rows) gid1 = gids[r1];
        } else {
            if (r0 < rows) sc0 = g_inv_src[r0];
            if (r1 < rows) sc1 = g_inv_src[r1];
        }
        #pragma unroll
        for (int nt = 0; nt < 8; ++nt) {
            const float* a = acc[mt * 8 + nt];
            int col = base_n + nt * 8 + ((lane & 3) << 1);
            float2 bb = *reinterpret_cast<const float2*>(&bias[col]);
            float o0x = fmaxf(a[0] + bb.x, 0.f);
            float o0y = fmaxf(a[1] + bb.y, 0.f);
            float o1x = fmaxf(a[2] + bb.x, 0.f);
            float o1y = fmaxf(a[3] + bb.y, 0.f);
            if (EPI == 0) {
                if (r0 < rows)
                    *reinterpret_cast<__half2*>(g_h16 + (size_t)r0 * 128 + col) =
                        __floats2half2_rn(o0x * sc0, o0y * sc0);
                if (r1 < rows)
                    *reinterpret_cast<__half2*>(g_h16 + (size_t)r1 * 128 + col) =
                        __floats2half2_rn(o1x * sc1, o1y * sc1);
            } else {
                if (gid0 >= 0) {
                    atomicAdd(g_emb + (size_t)gid0 * 128 + col,     o0x);
                    atomicAdd(g_emb + (size_t)gid0 * 128 + col + 1, o0y);
                }
                if (gid1 >= 0) {
                    atomicAdd(g_emb + (size_t)gid1 * 128 + col,     o1x);
                    atomicAdd(g_emb + (size_t)gid1 * 128 + col + 1, o1y);
                }
            }
        }
    }
}

// ---------------- MLP head (NORM: divide X rows by graph counts) ----------------
template <bool NORM>
__global__ void k_mlp(const float* __restrict__ X, const float* __restrict__ W,
                      const float* __restrict__ b, float* __restrict__ Y,
                      int K, int M) {
    int idx = blockIdx.x * blockDim.x + threadIdx.x;
    int c = idx % M;
    int g0 = (idx / M) * 8;
    if (g0 >= kG) return;
    float acc[8];
    #pragma unroll
    for (int j = 0; j < 8; ++j) acc[j] = 0.f;
    for (int k = 0; k < K; ++k) {
        float w = W[(size_t)k * M + c];
        #pragma unroll
        for (int j = 0; j < 8; ++j)
            acc[j] += X[(size_t)(g0 + j) * K + k] * w;
    }
    float bias = b[c];
    #pragma unroll
    for (int j = 0; j < 8; ++j) {
        float v = acc[j];
        if (NORM) v *= 1.f / (float)max(g_gcnt[g0 + j], 1);
        Y[(size_t)(g0 + j) * M + c] = fmaxf(v + bias, 0.f);
    }
}

__global__ void k_final(const float* __restrict__ X, const float* __restrict__ W,
                        const float* __restrict__ b, float* __restrict__ out) {
    int g = (blockIdx.x * blockDim.x + threadIdx.x) >> 5;
    int lane = threadIdx.x & 31;
    if (g >= kG) return;
    float s = 0.f;
    #pragma unroll
    for (int k = lane; k < 256; k += 32) s += X[(size_t)g * 256 + k] * W[k];
    #pragma unroll
    for (int off = 16; off; off >>= 1) s += __shfl_down_sync(0xffffffffu, s, off);
    if (lane == 0) out[g] = s + b[0];
}

// ---------------- launch ----------------
extern "C" void kernel_launch(void* const* d_in, const int* in_sizes, int n_in,
                              void* d_out, int out_size) {
    const float* feats = (const float*)d_in[0];
    const int*   src   = (const int*)d_in[1];
    const int*   dst   = (const int*)d_in[2];
    const int*   gids  = (const int*)d_in[3];
    const float* W0 = (const float*)d_in[4];  const float* b0 = (const float*)d_in[5];
    const float* W1 = (const float*)d_in[6];  const float* b1 = (const float*)d_in[7];
    const float* W2 = (const float*)d_in[8];  const float* b2 = (const float*)d_in[9];
    const float* Wm0 = (const float*)d_in[10]; const float* bm0 = (const float*)d_in[11];
    const float* Wm1 = (const float*)d_in[12]; const float* bm1 = (const float*)d_in[13];
    const float* Wm2 = (const float*)d_in[14]; const float* bm2 = (const float*)d_in[15];
    float* out = (float*)d_out;

    float *emb, *x1, *x2;
    __half *whi, *wlo;
    cudaGetSymbolAddress((void**)&emb,  g_emb);
    cudaGetSymbolAddress((void**)&x1,   g_x1);
    cudaGetSymbolAddress((void**)&x2,   g_x2);
    cudaGetSymbolAddress((void**)&whi,  g_whi);
    cudaGetSymbolAddress((void**)&wlo,  g_wlo);

    cudaFuncSetAttribute(k_gemm_mma<0>, cudaFuncAttributeMaxDynamicSharedMemorySize,
                         kMmaSmemBytes);
    cudaFuncSetAttribute(k_gemm_mma<1>, cudaFuncAttributeMaxDynamicSharedMemorySize,
                         kMmaSmemBytes);

    const int T = 256;
    int nBlkN = (kN + T - 1) / T;           // 391
    int nBlkWarpN = (kN * 32 + T - 1) / T;  // 12500
    int nBlkTc = (kN + 127) / 128;          // 782

    k_zero_wsplit<<<kBlkZ + 192, T>>>(W0, W1, W2);
    k_degrees<<<kBlkE, T>>>(src, dst);
    k_scan1<<<kScanBlocks, 1024>>>();
    k_scan_add_inv<<<nBlkN, T>>>(gids);
    k_scatter_f2h<<<kBlkE + kBlkH, T>>>(src, dst, feats);

    k_gather<<<nBlkWarpN, T>>>();
    k_gemm_mma<0><<<nBlkTc, T, kMmaSmemBytes>>>(whi + 0 * kD * kD, wlo + 0 * kD * kD,
                                                b0, gids, kN);
    k_gather<<<nBlkWarpN, T>>>();
    k_gemm_mma<0><<<nBlkTc, T, kMmaSmemBytes>>>(whi + 1 * kD * kD, wlo + 1 * kD * kD,
                                                b1, gids, kN);
    k_gather<<<nBlkWarpN, T>>>();
    k_gemm_mma<1><<<nBlkTc, T, kMmaSmemBytes>>>(whi + 2 * kD * kD, wlo + 2 * kD * kD,
                                                b2, gids, kN);

    k_mlp<true><<<(kG / 8) * 512 / T, T>>>(emb, Wm0, bm0, x1, 128, 512);
    k_mlp<false><<<(kG / 8) * 256 / T, T>>>(x1, Wm1, bm1, x2, 512, 256);
    k_final<<<(kG * 32) / T, T>>>(x2, Wm2, bm2, out);
}